// round 15
// baseline (speedup 1.0000x reference)
#include <cuda_runtime.h>
#include <cstdint>

// CTC loss forward, single fused kernel, producer/consumer within each block.
// 64 blocks (one per batch), 9 warps. Warps 1-8 gather emissions with
// cp.async (4B scattered, fire-and-forget: all 8 groups of 4 rows committed
// before any wait) into smem sm[t][0..31]=lp[t,b,c1(l)], sm[t][32]=blank,
// rows striped t%8; then drain groups in order (wait_group 7..0), exp IN
// PLACE, bar g+1 after group g guarantees rows <= 32g+31 exp'd; bar 9 = all.
// Warp 0: linear-domain fused-pair recursion off LDS; lane l owns states 2l
// ("e"), 2l+1 ("o"); lane 31 also state 64 ("a2"). Consumer segment s
// (8 quads; prefetch rows <= 32s+36) waits bar s+2; tail waits bar 9.
// Exact pow2 rescale every 4 steps (redux.sync.max.s32), lag-applied.

constexpr int B_SZ  = 64;
constexpr int C_SZ  = 8000;
constexpr int L_MAX = 32;
constexpr int ROW   = 33;
constexpr int NTHR  = 288;

__device__ float g_loss[B_SZ];
__device__ int   g_count;

__device__ __forceinline__ int warp_max_s32(int v) {
    int r;
    asm volatile("redux.sync.max.s32 %0, %1, 0xffffffff;" : "=r"(r) : "r"(v));
    return r;
}
__device__ __forceinline__ float shup(float v, int d) {
    return __shfl_up_sync(0xffffffffu, v, d);
}

struct QB { float p1[4], pb[4], pmA, pmB; };

__device__ __forceinline__ void loadq(const float* __restrict__ sm, int q,
                                      int l, float m0, QB& d) {
    const int r0 = 4 * q + 1;            // rows r0..r0+3; pad row covers 256
#pragma unroll
    for (int j = 0; j < 4; j++) {
        d.p1[j] = sm[(r0 + j) * ROW + l];
        d.pb[j] = sm[(r0 + j) * ROW + 32];
    }
    // l==0 reads [r*ROW-1] = previous row's blank slot; masked by m0
    d.pmA = sm[r0 * ROW + l - 1] * m0;
    d.pmB = sm[(r0 + 2) * ROW + l - 1] * m0;
}

__device__ __forceinline__ void do_quad(float& e, float& o, float& a2,
                                        const QB& c, float skf, float skfm,
                                        float m0, float m1) {
#pragma unroll
    for (int h = 0; h < 2; h++) {        // two fused pairs = 4 steps
        const float pm  = h ? c.pmB : c.pmA;
        const float p1a = c.p1[2 * h],     pba = c.pb[2 * h];
        const float p1b = c.p1[2 * h + 1], pbb = c.pb[2 * h + 1];
        const float x1  = shup(o, 1) * m0;
        const float x2  = shup(o, 2) * m1;
        const float y1  = shup(e, 1);
        const float otm = ((x1 + y1) + skfm * x2) * pm;
        const float et  = (e + x1) * pba;
        const float ot  = ((o + e) + skf * x1) * p1a;
        const float at  = (a2 + o) * pba;
        e  = (et + otm) * pbb;
        o  = ((ot + et) + skf * otm) * p1b;
        a2 = (at + ot) * pbb;
    }
}

__device__ __forceinline__ void rescale(float& e, float& o, float& a2,
                                        int& g, float& fpend, int& fexp) {
    e *= fpend; o *= fpend; a2 *= fpend; g += fexp;
    const int mi = warp_max_s32(__float_as_int(fmaxf(e, fmaxf(o, a2))));
    int fx = 207 - ((mi >> 23) & 0xff);              // 80 - E, exact pow2
    fx = fx > 127 ? 127 : (fx < -126 ? -126 : fx);
    fpend = __int_as_float((fx + 127) << 23);
    fexp  = fx;
}

// drain group G (wait_group N pending), exp in place, arrive bar G+1
#define DRAIN_GROUP(G, N)                                                     \
    do {                                                                      \
        asm volatile("cp.async.wait_group %0;" :: "n"(N) : "memory");         \
        _Pragma("unroll")                                                     \
        for (int j = 0; j < 4; j++) {                                         \
            const int r = pw + 8 * (4 * (G) + j);                             \
            sm[r * ROW + l] = __expf(sm[r * ROW + l]);                        \
            if (l == 0) sm[r * ROW + 32] = __expf(sm[r * ROW + 32]);          \
        }                                                                     \
        asm volatile("bar.arrive %0, 288;" :: "n"((G) + 1) : "memory");       \
    } while (0)

__global__ void __launch_bounds__(NTHR, 1)
ctc_kernel(const float* __restrict__ lp,
           const int*   __restrict__ targets,
           const int*   __restrict__ in_len,
           const int*   __restrict__ tgt_len,
           float*       __restrict__ out) {
    __shared__ float sm[257 * ROW];                 // 256 rows + 1 pad row
    const int b   = blockIdx.x;
    const int tid = threadIdx.x;
    const int l   = tid & 31;
    const int w   = tid >> 5;
    const size_t BC = (size_t)B_SZ * C_SZ;

    const int tl   = tgt_len[b];
    const int last = in_len[b] - 1;                 // in [128, 255]
    const int c1   = (l < tl) ? targets[b * L_MAX + l] : 0;

    if (w > 0) {
        // ---- producer warp pw: rows t = pw + 8k, k = 0..31 ----
        const int pw = w - 1;
        const float* pbp = lp + (size_t)pw * BC + (size_t)b * C_SZ;
        const float* p1p = pbp + c1;
        const uint32_t sbase = (uint32_t)__cvta_generic_to_shared(sm);

        // issue ALL 8 groups of 4 rows (fire-and-forget; ~4.2k lines in flight)
#pragma unroll
        for (int g = 0; g < 8; g++) {
#pragma unroll
            for (int j = 0; j < 4; j++) {
                const int k = 4 * g + j;
                const int r = pw + 8 * k;
                const uint32_t dst = sbase + (uint32_t)(r * ROW + l) * 4u;
                asm volatile("cp.async.ca.shared.global [%0], [%1], 4;"
                             :: "r"(dst), "l"(p1p + (size_t)k * 8 * BC));
                if (l == 0)
                    asm volatile("cp.async.ca.shared.global [%0], [%1], 4;"
                                 :: "r"(sbase + (uint32_t)(r * ROW + 32) * 4u),
                                    "l"(pbp + (size_t)k * 8 * BC));
            }
            asm volatile("cp.async.commit_group;");
        }
        // drain in commit order, exp in place, publish
        DRAIN_GROUP(0, 7); DRAIN_GROUP(1, 6); DRAIN_GROUP(2, 5); DRAIN_GROUP(3, 4);
        DRAIN_GROUP(4, 3); DRAIN_GROUP(5, 2); DRAIN_GROUP(6, 1); DRAIN_GROUP(7, 0);
        asm volatile("bar.arrive 9, 288;" ::: "memory");
        return;
    }

    // ---- consumer warp ----
    const int  c1p  = __shfl_up_sync(0xffffffffu, c1, 1);
    const bool skip = (c1 != 0) && ((l == 0) || (c1 != c1p));
    const float skf  = skip ? 1.f : 0.f;
    const float skfm = shup(skf, 1);
    const float m0   = (l == 0) ? 0.f : 1.f;
    const float m1   = (l <= 1) ? 0.f : 1.f;

    asm volatile("bar.sync 1, 288;" ::: "memory");  // rows <= 31 exp'd

    // t=0 init (prob domain, pre-scaled 2^80)
    float e = 0.f, o = 0.f, a2 = 0.f;
    if (l == 0) {
        e = sm[32] * 0x1p80f;
        o = (tl > 0) ? sm[0] * 0x1p80f : 0.f;
    }
    int g = 80;
    float fpend = 1.f;
    int   fexp  = 0;

    const int nq  = last >> 2;                      // in [32, 63]
    const int rem = last & 3;

    QB A, Bq;
    loadq(sm, 0, l, m0, A);

    int q = 0;
#pragma unroll 1
    for (int s = 0; s < 7; s++) {                   // 8-quad segments
        if (q + 1 >= nq) break;
        asm volatile("bar.sync %0, 288;" :: "r"(s + 2) : "memory");
        const int qend = min(nq, 8 * (s + 1));
        while (q + 1 < qend) {                      // quads in ping/pong pairs
            rescale(e, o, a2, g, fpend, fexp);      // every 4 steps, lagged
            loadq(sm, q + 1, l, m0, Bq);
            do_quad(e, o, a2, A, skf, skfm, m0, m1);  q++;
            rescale(e, o, a2, g, fpend, fexp);
            loadq(sm, q + 1, l, m0, A);
            do_quad(e, o, a2, Bq, skf, skfm, m0, m1); q++;
        }
    }
    asm volatile("bar.sync 9, 288;" ::: "memory");  // all rows exp'd
    while (q + 1 < nq) {
        rescale(e, o, a2, g, fpend, fexp);
        loadq(sm, q + 1, l, m0, Bq);
        do_quad(e, o, a2, A, skf, skfm, m0, m1);  q++;
        rescale(e, o, a2, g, fpend, fexp);
        loadq(sm, q + 1, l, m0, A);
        do_quad(e, o, a2, Bq, skf, skfm, m0, m1); q++;
    }
    if (q < nq) {                                   // leftover quad (nq odd)
        rescale(e, o, a2, g, fpend, fexp);
        loadq(sm, q + 1, l, m0, Bq);
        do_quad(e, o, a2, A, skf, skfm, m0, m1);  q++;
    }

    // epilogue: rem steps; quad-nq data sits in A (nq even) or Bq (nq odd)
    float ep1[3], epb[3];
#pragma unroll
    for (int j = 0; j < 3; j++) {
        ep1[j] = (nq & 1) ? Bq.p1[j] : A.p1[j];
        epb[j] = (nq & 1) ? Bq.pb[j] : A.pb[j];
    }
#pragma unroll
    for (int j = 0; j < 3; j++) {
        if (j < rem) {
            const float x1 = shup(o, 1) * m0;
            const float en = (e + x1) * epb[j];
            const float on = ((o + e) + skf * x1) * ep1[j];
            const float an = (a2 + o) * epb[j];
            e = en; o = on; a2 = an;
        }
    }

    // final states: i_blank = 2*tl (e @ lane tl, or a2 @ lane31 if tl==32),
    //               i_char  = 2*tl-1 (o @ lane tl-1)
    const float vbl = __shfl_sync(0xffffffffu, e, tl & 31);
    const float vbh = __shfl_sync(0xffffffffu, a2, 31);
    const float vb  = (tl >= 32) ? vbh : vbl;
    const int   icl = (tl > 0) ? (tl - 1) : 0;
    const float vc  = __shfl_sync(0xffffffffu, o, icl);
    const float tot = (tl > 0) ? (vb + vc) : vb;

    if (l == 0) {
        const float total_log = logf(tot) - (float)g * 0.69314718055994531f;
        const int   denom     = (tl > 0) ? tl : 1;
        g_loss[b] = -total_log / (float)denom;
        __threadfence();
        const int old = atomicAdd(&g_count, 1);
        if (old == B_SZ - 1) {
            g_count = 0;                            // reset for next graph replay
            __threadfence();
            float s = 0.f;
            for (int i = 0; i < B_SZ; i++) s += __ldcg((const float*)&g_loss[i]);
            out[0] = s / (float)B_SZ;
        }
    }
}

extern "C" void kernel_launch(void* const* d_in, const int* in_sizes, int n_in,
                              void* d_out, int out_size) {
    const float* log_probs  = (const float*)d_in[0];
    const int*   targets    = (const int*)d_in[1];
    const int*   input_len  = (const int*)d_in[2];
    const int*   target_len = (const int*)d_in[3];
    float* out = (float*)d_out;
    (void)in_sizes; (void)n_in; (void)out_size;

    ctc_kernel<<<B_SZ, NTHR>>>(log_probs, targets, input_len, target_len, out);
}

// round 16
// speedup vs baseline: 1.1555x; 1.1555x over previous
#include <cuda_runtime.h>
#include <cstdint>

// CTC loss forward. 128 blocks, one wave.
// Block b (<64): scan block. Warp 0 = consumer: linear-domain fused-pair CTC
//   recursion; smem is TRANSPOSED (plane per state, stride PL=260 floats;
//   plane 0 = zeroed guard so lane0's neighbor emission is naturally 0;
//   planes 1..32 = odd-state emissions per lane; plane 33 = blank). Row t
//   stored at index t-1; t=0 emissions loaded directly by the consumer.
//   loadq = 3x LDS.128. Exact pow2 rescale every 4 steps (redux.sync.max.s32
//   on float bits), lag-applied. Warps 1-8: gather+exp t=1..128 (4 groups,
//   bars 1..4 -> idx<=31/63/95/127), then copy t=129..255 from g_em in 4
//   segments (flag poll: lane0 + nanosleep; bars 5..8 -> idx<=159/191/223/255),
//   bar 9 = all.
// Block 64+b: helper. Warps 0-7 gather+exp t=129..255 into g_em[b][t-129],
//   publishing 4 segments via threadfence+flag. Flags reset by the consumer
//   after bar 9 (producers provably past their polls).

constexpr int B_SZ  = 64;
constexpr int C_SZ  = 8000;
constexpr int L_MAX = 32;
constexpr int PL    = 260;               // plane stride in floats (16B-aligned)
constexpr int NTHR  = 288;

__device__ float g_em[B_SZ][128][33];
__device__ int   g_flag[B_SZ][4];
__device__ float g_loss[B_SZ];
__device__ int   g_count;

__device__ __forceinline__ int warp_max_s32(int v) {
    int r;
    asm volatile("redux.sync.max.s32 %0, %1, 0xffffffff;" : "=r"(r) : "r"(v));
    return r;
}
__device__ __forceinline__ float shup(float v, int d) {
    return __shfl_up_sync(0xffffffffu, v, d);
}

struct QB { float4 p1, pb, pm; };

__device__ __forceinline__ void loadq(const float* __restrict__ sm, int q,
                                      int l, QB& d) {
    const int idx = 4 * q;               // steps 4q+1..4q+4 live at idx..idx+3
    d.p1 = *(const float4*)(sm + (l + 1) * PL + idx);
    d.pb = *(const float4*)(sm + 33 * PL + idx);
    d.pm = *(const float4*)(sm + l * PL + idx);   // lane0 -> guard plane = 0
}

__device__ __forceinline__ void do_quad(float& e, float& o, float& a2,
                                        const QB& c, float skf, float skfm_m,
                                        float m0) {
#pragma unroll
    for (int h = 0; h < 2; h++) {        // two fused pairs = 4 steps
        const float pm  = h ? c.pm.z : c.pm.x;
        const float p1a = h ? c.p1.z : c.p1.x;
        const float pba = h ? c.pb.z : c.pb.x;
        const float p1b = h ? c.p1.w : c.p1.y;
        const float pbb = h ? c.pb.w : c.pb.y;
        const float x1  = shup(o, 1);            // raw; masked via pm / x1m
        const float x2  = shup(o, 2);            // raw; masked via skfm_m
        const float y1  = shup(e, 1);
        const float x1m = x1 * m0;
        const float otm = ((x1 + y1) + skfm_m * x2) * pm;  // lane0: pm==0
        const float et  = (e + x1m) * pba;
        const float ot  = ((o + e) + skf * x1m) * p1a;
        const float at  = (a2 + o) * pba;
        e  = (et + otm) * pbb;
        o  = ((ot + et) + skf * otm) * p1b;
        a2 = (at + ot) * pbb;
    }
}

__device__ __forceinline__ void rescale(float& e, float& o, float& a2,
                                        int& g, float& fpend, int& fexp) {
    e *= fpend; o *= fpend; a2 *= fpend; g += fexp;
    const int mi = warp_max_s32(__float_as_int(fmaxf(e, fmaxf(o, a2))));
    int fx = 207 - ((mi >> 23) & 0xff);              // 80 - E, exact pow2
    fx = fx > 127 ? 127 : (fx < -126 ? -126 : fx);
    fpend = __int_as_float((fx + 127) << 23);
    fexp  = fx;
}

__global__ void __launch_bounds__(NTHR, 1)
ctc_kernel(const float* __restrict__ lp,
           const int*   __restrict__ targets,
           const int*   __restrict__ in_len,
           const int*   __restrict__ tgt_len,
           float*       __restrict__ out) {
    __shared__ __align__(16) float sm[34 * PL];     // 35360 B
    const int tid = threadIdx.x;
    const int l   = tid & 31;
    const int w   = tid >> 5;
    const size_t BC = (size_t)B_SZ * C_SZ;

    // ---------------- helper blocks: gather t=129..255 into g_em ----------
    if (blockIdx.x >= B_SZ) {
        const int b  = blockIdx.x - B_SZ;
        const int tl = tgt_len[b];
        const int c1 = (l < tl) ? targets[b * L_MAX + l] : 0;
        const float* base = lp + (size_t)b * C_SZ;

#pragma unroll
        for (int s = 0; s < 4; s++) {
            if (w < 8) {
                float v1[4], vb4[4];
#pragma unroll
                for (int j = 0; j < 4; j++) {
                    const int t = 129 + w + 8 * (4 * s + j);
                    if (t < 256) {
                        v1[j]  = __ldg(base + (size_t)t * BC + c1);
                        vb4[j] = __ldg(base + (size_t)t * BC);
                    }
                }
#pragma unroll
                for (int j = 0; j < 4; j++) {
                    const int t = 129 + w + 8 * (4 * s + j);
                    if (t < 256) {
                        const int k = t - 129;
                        g_em[b][k][l] = __expf(v1[j]);
                        if (l == 0) g_em[b][k][32] = __expf(vb4[j]);
                    }
                }
                __threadfence();
            }
            __syncthreads();
            if (tid == 0) *(volatile int*)&g_flag[b][s] = 1;
        }
        return;
    }

    // ---------------- scan blocks ----------------
    const int b    = blockIdx.x;
    const int tl   = tgt_len[b];
    const int last = in_len[b] - 1;                 // in [128, 255]
    const int c1   = (l < tl) ? targets[b * L_MAX + l] : 0;

    if (w > 0) {
        // ---- producer warp pw: gather t = 1+pw+8k, k=0..15 (t<=128) ----
        const int pw = w - 1;
        const float* base = lp + (size_t)b * C_SZ;

        if (pw == 0) {                              // zero guard plane 0
#pragma unroll
            for (int k = 0; k < 9; k++) {
                const int i = 32 * k + l;
                if (i < PL) sm[i] = 0.f;
            }
        }
#pragma unroll
        for (int g = 0; g < 4; g++) {               // bar g+1: idx <= 32g+31
            float v1[4], vb4[4];
#pragma unroll
            for (int j = 0; j < 4; j++) {
                const int t = 1 + pw + 8 * (4 * g + j);
                v1[j]  = __ldg(base + (size_t)t * BC + c1);
                vb4[j] = __ldg(base + (size_t)t * BC);
            }
#pragma unroll
            for (int j = 0; j < 4; j++) {
                const int t   = 1 + pw + 8 * (4 * g + j);
                const int idx = t - 1;
                sm[(l + 1) * PL + idx] = __expf(v1[j]);
                if (l == 0) sm[33 * PL + idx] = __expf(vb4[j]);
            }
            asm volatile("bar.arrive %0, 288;" :: "r"(g + 1) : "memory");
        }
        // ---- copy t=129..255 from g_em (bars 5..8) ----
#pragma unroll
        for (int s = 0; s < 4; s++) {
            if (l == 0)
                while (*(volatile int*)&g_flag[b][s] == 0) __nanosleep(64);
            __syncwarp();
            __threadfence();                        // acquire
#pragma unroll
            for (int j = 0; j < 4; j++) {
                const int k   = 32 * s + pw * 4 + j;
                const int idx = 128 + k;            // t = 129+k
                sm[(l + 1) * PL + idx] = __ldcg(&g_em[b][k][l]);
                if (l == 0) sm[33 * PL + idx] = __ldcg(&g_em[b][k][32]);
            }
            asm volatile("bar.arrive %0, 288;" :: "r"(s + 5) : "memory");
        }
        asm volatile("bar.arrive 9, 288;" ::: "memory");
        return;
    }

    // ---- consumer warp ----
    const int  c1p  = __shfl_up_sync(0xffffffffu, c1, 1);
    const bool skip = (c1 != 0) && ((l == 0) || (c1 != c1p));
    const float skf    = skip ? 1.f : 0.f;
    const float m0     = (l == 0) ? 0.f : 1.f;
    const float skfm_m = shup(skf, 1) * ((l <= 1) ? 0.f : 1.f);

    // t=0 emissions: direct loads (issued before the barrier wait)
    float vb0 = 0.f, vc0 = 0.f;
    if (l == 0) {
        vb0 = __ldg(lp + (size_t)b * C_SZ);
        vc0 = __ldg(lp + (size_t)b * C_SZ + c1);
    }

    asm volatile("bar.sync 1, 288;" ::: "memory");  // idx <= 31 available

    float e = 0.f, o = 0.f, a2 = 0.f;
    if (l == 0) {
        e = __expf(vb0) * 0x1p80f;
        o = (tl > 0) ? __expf(vc0) * 0x1p80f : 0.f;
    }
    int g = 80;
    float fpend = 1.f;
    int   fexp  = 0;

    const int nq  = last >> 2;                      // in [32, 63]
    const int rem = last & 3;

    QB A, Bq;
    loadq(sm, 0, l, A);

    int q = 0;
#pragma unroll 1
    for (int s = 0; s < 7; s++) {                   // 8-quad segments
        if (q + 1 >= nq) break;
        asm volatile("bar.sync %0, 288;" :: "r"(s + 2) : "memory");
        const int qend = min(nq, 8 * (s + 1));
        while (q + 1 < qend) {                      // quads in ping/pong pairs
            rescale(e, o, a2, g, fpend, fexp);      // every 4 steps, lagged
            loadq(sm, q + 1, l, Bq);
            do_quad(e, o, a2, A, skf, skfm_m, m0);  q++;
            rescale(e, o, a2, g, fpend, fexp);
            loadq(sm, q + 1, l, A);
            do_quad(e, o, a2, Bq, skf, skfm_m, m0); q++;
        }
    }
    asm volatile("bar.sync 9, 288;" ::: "memory");  // all rows ready
    while (q + 1 < nq) {
        rescale(e, o, a2, g, fpend, fexp);
        loadq(sm, q + 1, l, Bq);
        do_quad(e, o, a2, A, skf, skfm_m, m0);  q++;
        rescale(e, o, a2, g, fpend, fexp);
        loadq(sm, q + 1, l, A);
        do_quad(e, o, a2, Bq, skf, skfm_m, m0); q++;
    }
    if (q < nq) {                                   // leftover quad (nq odd)
        rescale(e, o, a2, g, fpend, fexp);
        loadq(sm, q + 1, l, Bq);
        do_quad(e, o, a2, A, skf, skfm_m, m0);  q++;
    }

    // epilogue: rem steps; quad-nq data sits in A (nq even) or Bq (nq odd)
    const float* sp1 = (nq & 1) ? (const float*)&Bq.p1 : (const float*)&A.p1;
    const float* spb = (nq & 1) ? (const float*)&Bq.pb : (const float*)&A.pb;
#pragma unroll
    for (int j = 0; j < 3; j++) {
        if (j < rem) {
            const float x1 = shup(o, 1) * m0;
            const float en = (e + x1) * spb[j];
            const float on = ((o + e) + skf * x1) * sp1[j];
            const float an = (a2 + o) * spb[j];
            e = en; o = on; a2 = an;
        }
    }

    // final states: i_blank = 2*tl (e @ lane tl, or a2 @ lane31 if tl==32),
    //               i_char  = 2*tl-1 (o @ lane tl-1)
    const float vbl = __shfl_sync(0xffffffffu, e, tl & 31);
    const float vbh = __shfl_sync(0xffffffffu, a2, 31);
    const float vb  = (tl >= 32) ? vbh : vbl;
    const int   icl = (tl > 0) ? (tl - 1) : 0;
    const float vc  = __shfl_sync(0xffffffffu, o, icl);
    const float tot = (tl > 0) ? (vb + vc) : vb;

    if (l == 0) {
        // reset flags for the next graph replay (producers are past bar 9)
#pragma unroll
        for (int s = 0; s < 4; s++) *(volatile int*)&g_flag[b][s] = 0;

        const float total_log = logf(tot) - (float)g * 0.69314718055994531f;
        const int   denom     = (tl > 0) ? tl : 1;
        g_loss[b] = -total_log / (float)denom;
        __threadfence();
        const int old = atomicAdd(&g_count, 1);
        if (old == B_SZ - 1) {
            g_count = 0;                            // reset for next graph replay
            __threadfence();
            float s = 0.f;
            for (int i = 0; i < B_SZ; i++) s += __ldcg((const float*)&g_loss[i]);
            out[0] = s / (float)B_SZ;
        }
    }
}

extern "C" void kernel_launch(void* const* d_in, const int* in_sizes, int n_in,
                              void* d_out, int out_size) {
    const float* log_probs  = (const float*)d_in[0];
    const int*   targets    = (const int*)d_in[1];
    const int*   input_len  = (const int*)d_in[2];
    const int*   target_len = (const int*)d_in[3];
    float* out = (float*)d_out;
    (void)in_sizes; (void)n_in; (void)out_size;

    ctc_kernel<<<2 * B_SZ, NTHR>>>(log_probs, targets, input_len, target_len, out);
}